// round 6
// baseline (speedup 1.0000x reference)
#include <cuda_runtime.h>
#include <math.h>
#include <stdint.h>

// Problem constants (fixed shapes)
constexpr int Bsz  = 2;
constexpr int Sseq = 2048;
constexpr int Fdim = 1024;
constexpr int Hh   = 16;
constexpr int Dh   = 64;
constexpr int Mrows = Bsz * Sseq;   // 4096

// Scratch (allocation-free: device globals). All GEMM/flash operands are
// kept pre-split as tf32 hi (rna-rounded fp32 bits) + lo (fp32 residual).
__device__ float g_Xfhi[(size_t)Mrows * Fdim];
__device__ float g_Xflo[(size_t)Mrows * Fdim];
__device__ float g_Xthi[(size_t)Mrows * Fdim];
__device__ float g_Xtlo[(size_t)Mrows * Fdim];
__device__ float g_Wqhi[(size_t)Fdim * Fdim];
__device__ float g_Wqlo[(size_t)Fdim * Fdim];
__device__ float g_Wkvhi[(size_t)Fdim * 2 * Fdim];
__device__ float g_Wkvlo[(size_t)Fdim * 2 * Fdim];
__device__ float g_Wohi[(size_t)Fdim * Fdim];
__device__ float g_Wolo[(size_t)Fdim * Fdim];
__device__ float g_Qhi[(size_t)Mrows * Fdim];
__device__ float g_Qlo[(size_t)Mrows * Fdim];
__device__ float g_Khi[(size_t)Mrows * Fdim];
__device__ float g_Klo[(size_t)Mrows * Fdim];
__device__ float g_Vhi[(size_t)Mrows * Fdim];
__device__ float g_Vlo[(size_t)Mrows * Fdim];
__device__ float g_Ohi[(size_t)Mrows * Fdim];
__device__ float g_Olo[(size_t)Mrows * Fdim];

// ---------------------------------------------------------------------------
// Common PTX helpers
// ---------------------------------------------------------------------------
__device__ __forceinline__ void cp_async16(uint32_t saddr, const void* gptr) {
    asm volatile("cp.async.cg.shared.global [%0], [%1], 16;"
                 :: "r"(saddr), "l"(gptr));
}
__device__ __forceinline__ void cp_commit() {
    asm volatile("cp.async.commit_group;");
}
__device__ __forceinline__ void cp_wait0() {
    asm volatile("cp.async.wait_group 0;");
}
__device__ __forceinline__ void cp_wait1() {
    asm volatile("cp.async.wait_group 1;");
}

__device__ __forceinline__ uint32_t f2tf32(float x) {
    uint32_t r;
    asm("cvt.rna.tf32.f32 %0, %1;" : "=r"(r) : "f"(x));
    return r;
}

__device__ __forceinline__ void mma_tf32(
    float& d0, float& d1, float& d2, float& d3,
    uint32_t a0, uint32_t a1, uint32_t a2, uint32_t a3,
    uint32_t b0, uint32_t b1)
{
    asm volatile(
        "mma.sync.aligned.m16n8k8.row.col.f32.tf32.tf32.f32 "
        "{%0,%1,%2,%3},{%4,%5,%6,%7},{%8,%9},{%0,%1,%2,%3};"
        : "+f"(d0), "+f"(d1), "+f"(d2), "+f"(d3)
        : "r"(a0), "r"(a1), "r"(a2), "r"(a3), "r"(b0), "r"(b1));
}

// ---------------------------------------------------------------------------
// Elementwise tf32 hi/lo split: src -> (hi, lo), float4-vectorized.
// ---------------------------------------------------------------------------
__global__ __launch_bounds__(256) void split_kernel(
    const float* __restrict__ src, float* __restrict__ hi,
    float* __restrict__ lo, int n4)
{
    const int i = blockIdx.x * 256 + threadIdx.x;
    if (i >= n4) return;
    float4 v = ((const float4*)src)[i];
    uint32_t h0 = f2tf32(v.x), h1 = f2tf32(v.y);
    uint32_t h2 = f2tf32(v.z), h3 = f2tf32(v.w);
    float4 hv = make_float4(__uint_as_float(h0), __uint_as_float(h1),
                            __uint_as_float(h2), __uint_as_float(h3));
    ((float4*)hi)[i] = hv;
    ((float4*)lo)[i] = make_float4(v.x - hv.x, v.y - hv.y,
                                   v.z - hv.z, v.w - hv.w);
}

// ---------------------------------------------------------------------------
// 3xTF32 GEMM core on PRE-SPLIT operands (zero cvt/sub in hot loop).
// 128x128 tile, BK=32, 8 warps of 64x32, cp.async double-buffered.
// smem stage: [AshH | AshL | BsH | BsL].
// ---------------------------------------------------------------------------
constexpr int SA = 36;
constexpr int SB = 132;
constexpr int AS_FLOATS = 128 * SA;                  // 4608
constexpr int BS_FLOATS = 32 * SB;                   // 4224
constexpr int STAGE_FLOATS = 2 * AS_FLOATS + 2 * BS_FLOATS;  // 17664
constexpr int GEMM_SMEM = 2 * STAGE_FLOATS * 4;      // 141312 B

template <typename EPI>
__device__ __forceinline__ void gemm_mainloop(
    const float* __restrict__ Ahi, const float* __restrict__ Alo,
    const float* __restrict__ Whi, const float* __restrict__ Wlo,
    int m0, int n0, int Kk, int Nn, float* sm, EPI epi)
{
    const uint32_t sbase = (uint32_t)__cvta_generic_to_shared(sm);
    const int tid  = threadIdx.x;
    const int warp = tid >> 5;
    const int lane = tid & 31;
    const int wm   = warp & 1;
    const int wn   = warp >> 1;
    const int rbase = wm * 64;
    const int cbase = wn * 32;
    const int lr = lane >> 2;
    const int lc = lane & 3;

    float acc[4][4][4];
    #pragma unroll
    for (int i = 0; i < 4; i++)
        #pragma unroll
        for (int j = 0; j < 4; j++)
            #pragma unroll
            for (int r = 0; r < 4; r++) acc[i][j][r] = 0.f;

    auto load_tile = [&](int kt, int st) {
        const int k0 = kt * 32;
        const uint32_t sAh = sbase + (uint32_t)(st * STAGE_FLOATS) * 4u;
        const uint32_t sAl = sAh + (uint32_t)AS_FLOATS * 4u;
        const uint32_t sBh = sAl + (uint32_t)AS_FLOATS * 4u;
        const uint32_t sBl = sBh + (uint32_t)BS_FLOATS * 4u;
        #pragma unroll
        for (int r = 0; r < 4; r++) {
            const int slot = r * 256 + tid;
            const int row = slot >> 3, k4 = slot & 7;
            const uint32_t so = (uint32_t)(row * SA + k4 * 4) * 4u;
            const size_t go = (size_t)(m0 + row) * Kk + k0 + k4 * 4;
            cp_async16(sAh + so, &Ahi[go]);
            cp_async16(sAl + so, &Alo[go]);
        }
        #pragma unroll
        for (int r = 0; r < 4; r++) {
            const int slot = r * 256 + tid;
            const int k = slot >> 5, n4 = slot & 31;
            const uint32_t so = (uint32_t)(k * SB + n4 * 4) * 4u;
            const size_t go = (size_t)(k0 + k) * Nn + n0 + n4 * 4;
            cp_async16(sBh + so, &Whi[go]);
            cp_async16(sBl + so, &Wlo[go]);
        }
    };

    const int NT = Kk / 32;
    load_tile(0, 0);
    cp_commit();

    for (int kt = 0; kt < NT; kt++) {
        cp_wait0();
        __syncthreads();
        if (kt + 1 < NT) { load_tile(kt + 1, (kt + 1) & 1); cp_commit(); }

        const uint32_t* AuH = (const uint32_t*)(sm + (kt & 1) * STAGE_FLOATS);
        const uint32_t* AuL = AuH + AS_FLOATS;
        const uint32_t* BuH = AuL + AS_FLOATS;
        const uint32_t* BuL = BuH + BS_FLOATS;

        #pragma unroll
        for (int ks = 0; ks < 4; ks++) {
            const int kk = ks * 8;
            uint32_t ah[4][4], al[4][4], bh[4][2], bl[4][2];
            #pragma unroll
            for (int mi = 0; mi < 4; mi++) {
                const int rr = rbase + mi * 16 + lr;
                const int o0 = rr * SA + kk + lc;
                const int o1 = (rr + 8) * SA + kk + lc;
                ah[mi][0] = AuH[o0];     al[mi][0] = AuL[o0];
                ah[mi][1] = AuH[o1];     al[mi][1] = AuL[o1];
                ah[mi][2] = AuH[o0 + 4]; al[mi][2] = AuL[o0 + 4];
                ah[mi][3] = AuH[o1 + 4]; al[mi][3] = AuL[o1 + 4];
            }
            #pragma unroll
            for (int nj = 0; nj < 4; nj++) {
                const int cc = cbase + nj * 8 + lr;
                const int o0 = (kk + lc) * SB + cc;
                const int o1 = (kk + lc + 4) * SB + cc;
                bh[nj][0] = BuH[o0]; bl[nj][0] = BuL[o0];
                bh[nj][1] = BuH[o1]; bl[nj][1] = BuL[o1];
            }
            #pragma unroll
            for (int mi = 0; mi < 4; mi++)
                #pragma unroll
                for (int nj = 0; nj < 4; nj++) {
                    mma_tf32(acc[mi][nj][0], acc[mi][nj][1],
                             acc[mi][nj][2], acc[mi][nj][3],
                             al[mi][0], al[mi][1], al[mi][2], al[mi][3],
                             bh[nj][0], bh[nj][1]);
                    mma_tf32(acc[mi][nj][0], acc[mi][nj][1],
                             acc[mi][nj][2], acc[mi][nj][3],
                             ah[mi][0], ah[mi][1], ah[mi][2], ah[mi][3],
                             bl[nj][0], bl[nj][1]);
                    mma_tf32(acc[mi][nj][0], acc[mi][nj][1],
                             acc[mi][nj][2], acc[mi][nj][3],
                             ah[mi][0], ah[mi][1], ah[mi][2], ah[mi][3],
                             bh[nj][0], bh[nj][1]);
                }
        }
        __syncthreads();
    }

    epi(acc, rbase, cbase, lr, lc);
}

// Merged Q + KV projection: grid.x = 768, writes hi/lo split outputs.
__global__ __launch_bounds__(256) void qkv_gemm_kernel(
    const float* __restrict__ Xfhi, const float* __restrict__ Xflo,
    const float* __restrict__ Xthi, const float* __restrict__ Xtlo,
    const float* __restrict__ Wqhi, const float* __restrict__ Wqlo,
    const float* __restrict__ Wkvhi, const float* __restrict__ Wkvlo,
    const float* __restrict__ bq, const float* __restrict__ bkv,
    float* __restrict__ Qhi, float* __restrict__ Qlo,
    float* __restrict__ Khi, float* __restrict__ Klo,
    float* __restrict__ Vhi, float* __restrict__ Vlo)
{
    extern __shared__ float sm[];
    const int bx = blockIdx.x;

    const float *Ahi, *Alo, *Whi, *Wlo, *bias;
    float *Dhi, *Dlo;
    int m0, n0, Nn, ncol;
    if (bx < 256) {
        Ahi = Xfhi; Alo = Xflo; Whi = Wqhi; Wlo = Wqlo; bias = bq; Nn = 1024;
        m0 = (bx >> 3) * 128; n0 = (bx & 7) * 128;
        Dhi = Qhi; Dlo = Qlo; ncol = n0;
    } else {
        const int bxx = bx - 256;
        Ahi = Xthi; Alo = Xtlo; Whi = Wkvhi; Wlo = Wkvlo; bias = bkv; Nn = 2048;
        m0 = (bxx >> 4) * 128; n0 = (bxx & 15) * 128;
        if (n0 < 1024) { Dhi = Khi; Dlo = Klo; ncol = n0; }
        else           { Dhi = Vhi; Dlo = Vlo; ncol = n0 - 1024; }
    }

    gemm_mainloop(Ahi, Alo, Whi, Wlo, m0, n0, Fdim, Nn, sm,
        [&](float (&acc)[4][4][4], int rbase, int cbase, int lr, int lc) {
            #pragma unroll
            for (int mi = 0; mi < 4; mi++) {
                const int row = m0 + rbase + mi * 16 + lr;
                #pragma unroll
                for (int nj = 0; nj < 4; nj++) {
                    const int col = ncol + cbase + nj * 8 + lc * 2;
                    const float bx0 = bias[n0 - ncol + col];
                    const float bx1 = bias[n0 - ncol + col + 1];
                    float v00 = acc[mi][nj][0] + bx0;
                    float v01 = acc[mi][nj][1] + bx1;
                    float v10 = acc[mi][nj][2] + bx0;
                    float v11 = acc[mi][nj][3] + bx1;
                    uint32_t h00 = f2tf32(v00), h01 = f2tf32(v01);
                    uint32_t h10 = f2tf32(v10), h11 = f2tf32(v11);
                    const size_t o0 = (size_t)row * 1024 + col;
                    const size_t o1 = (size_t)(row + 8) * 1024 + col;
                    *(float2*)&Dhi[o0] = make_float2(__uint_as_float(h00), __uint_as_float(h01));
                    *(float2*)&Dhi[o1] = make_float2(__uint_as_float(h10), __uint_as_float(h11));
                    *(float2*)&Dlo[o0] = make_float2(v00 - __uint_as_float(h00), v01 - __uint_as_float(h01));
                    *(float2*)&Dlo[o1] = make_float2(v10 - __uint_as_float(h10), v11 - __uint_as_float(h11));
                }
            }
        });
}

// Output projection: out = O @ w_out + b_out (pre-split inputs, fp32 store).
__global__ __launch_bounds__(256) void out_gemm_kernel(
    const float* __restrict__ Ahi, const float* __restrict__ Alo,
    const float* __restrict__ Whi, const float* __restrict__ Wlo,
    const float* __restrict__ bias, float* __restrict__ C)
{
    extern __shared__ float sm[];
    const int m0 = blockIdx.y * 128;
    const int n0 = blockIdx.x * 128;
    gemm_mainloop(Ahi, Alo, Whi, Wlo, m0, n0, Fdim, Fdim, sm,
        [&](float (&acc)[4][4][4], int rbase, int cbase, int lr, int lc) {
            #pragma unroll
            for (int mi = 0; mi < 4; mi++) {
                const int row = m0 + rbase + mi * 16 + lr;
                #pragma unroll
                for (int nj = 0; nj < 4; nj++) {
                    const int col = n0 + cbase + nj * 8 + lc * 2;
                    const float bx = bias[col], by = bias[col + 1];
                    *(float2*)&C[(size_t)row * Fdim + col] =
                        make_float2(acc[mi][nj][0] + bx, acc[mi][nj][1] + by);
                    *(float2*)&C[(size_t)(row + 8) * Fdim + col] =
                        make_float2(acc[mi][nj][2] + bx, acc[mi][nj][3] + by);
                }
            }
        });
}

// ---------------------------------------------------------------------------
// Tensor-core flash attention, pre-split operands. Br=128, Bc=64, d=64.
// S = 3 MMAs; O += 2 MMAs (P_lo*V dropped, ~1e-4 contribution).
// Mask: z >= s -> logit -1e12f; CTA t iterates 2t+2 kv tiles (t=0: all 32).
// Epilogue writes O as tf32 hi/lo for the output projection.
// ---------------------------------------------------------------------------
constexpr int KST = 68;
constexpr int VST = 72;
constexpr int PST = 68;
constexpr int KTILE = 64 * KST;
constexpr int VTILE = 64 * VST;
constexpr int KHI_OFF = 0;
constexpr int KLO_OFF = 2 * KTILE;
constexpr int VHI_OFF = 4 * KTILE;
constexpr int VLO_OFF = VHI_OFF + 2 * VTILE;
constexpr int PS_OFF  = VLO_OFF + 2 * VTILE;
constexpr int FLASH_FLOATS = PS_OFF + 128 * PST;
constexpr int FLASH_SMEM = FLASH_FLOATS * 4;      // 178176 B

__global__ __launch_bounds__(256) void flash_mma_kernel(
    const float* __restrict__ Qhi, const float* __restrict__ Qlo,
    const float* __restrict__ Khi, const float* __restrict__ Klo,
    const float* __restrict__ Vhi, const float* __restrict__ Vlo,
    float* __restrict__ Ohi, float* __restrict__ Olo)
{
    extern __shared__ float sm[];
    const uint32_t sbase = (uint32_t)__cvta_generic_to_shared(sm);
    float* Ps = sm + PS_OFF;

    const int x = blockIdx.x;
    const int t = (x == 0) ? 0 : (16 - x);       // heavy CTAs first
    const int h = blockIdx.y;
    const int b = blockIdx.z;
    const int tid  = threadIdx.x;
    const int warp = tid >> 5;
    const int lane = tid & 31;
    const int lq  = lane >> 2;
    const int lr4 = lane & 3;

    const size_t qoff = ((size_t)b * Sseq + (size_t)t * 128) * Fdim + h * Dh;
    const size_t koff = ((size_t)b * Sseq) * Fdim + h * Dh;

    auto load_kv = [&](int kc, int st) {
        const size_t base = koff + (size_t)(kc * 64) * Fdim;
        const uint32_t khd = sbase + (uint32_t)(KHI_OFF + st * KTILE) * 4u;
        const uint32_t kld = sbase + (uint32_t)(KLO_OFF + st * KTILE) * 4u;
        const uint32_t vhd = sbase + (uint32_t)(VHI_OFF + st * VTILE) * 4u;
        const uint32_t vld = sbase + (uint32_t)(VLO_OFF + st * VTILE) * 4u;
        #pragma unroll
        for (int r = 0; r < 4; r++) {
            const int slot = r * 256 + tid;
            const int row = slot >> 4;
            const int c4 = (slot & 15) * 4;
            const size_t g = base + (size_t)row * Fdim + c4;
            const uint32_t ks = (uint32_t)(row * KST + c4) * 4u;
            const uint32_t vs = (uint32_t)(row * VST + c4) * 4u;
            cp_async16(khd + ks, &Khi[g]);
            cp_async16(kld + ks, &Klo[g]);
            cp_async16(vhd + vs, &Vhi[g]);
            cp_async16(vld + vs, &Vlo[g]);
        }
    };

    auto stage_q = [&](const float* src) {
        #pragma unroll
        for (int r = 0; r < 8; r++) {
            const int slot = r * 256 + tid;
            const int row = slot >> 4;
            const int c4 = (slot & 15) * 4;
            cp_async16(sbase + (uint32_t)(PS_OFF + row * PST + c4) * 4u,
                       &src[qoff + (size_t)row * Fdim + c4]);
        }
    };

    stage_q(Qhi); cp_commit();
    load_kv(0, 0); cp_commit();

    uint32_t qh[8][4], ql[8][4];
    const float* Pw = Ps + warp * 16 * PST;

    cp_wait1();
    __syncthreads();
    #pragma unroll
    for (int kk = 0; kk < 8; kk++) {
        const int c = kk * 8 + lr4;
        qh[kk][0] = __float_as_uint(Pw[lq * PST + c]);
        qh[kk][1] = __float_as_uint(Pw[(lq + 8) * PST + c]);
        qh[kk][2] = __float_as_uint(Pw[lq * PST + c + 4]);
        qh[kk][3] = __float_as_uint(Pw[(lq + 8) * PST + c + 4]);
    }
    __syncthreads();
    stage_q(Qlo); cp_commit();
    cp_wait0();
    __syncthreads();
    #pragma unroll
    for (int kk = 0; kk < 8; kk++) {
        const int c = kk * 8 + lr4;
        ql[kk][0] = __float_as_uint(Pw[lq * PST + c]);
        ql[kk][1] = __float_as_uint(Pw[(lq + 8) * PST + c]);
        ql[kk][2] = __float_as_uint(Pw[lq * PST + c + 4]);
        ql[kk][3] = __float_as_uint(Pw[(lq + 8) * PST + c + 4]);
    }
    __syncthreads();

    float oacc[8][4];
    #pragma unroll
    for (int nt = 0; nt < 8; nt++)
        #pragma unroll
        for (int r = 0; r < 4; r++) oacc[nt][r] = 0.f;
    float m0 = -3.0e38f, m1 = -3.0e38f, l0 = 0.f, l1 = 0.f;

    const int row0 = t * 128 + warp * 16 + lq;
    const int row1 = row0 + 8;
    const int nkc = (t == 0) ? (Sseq / 64) : (2 * t + 2);

    for (int kc = 0; kc < nkc; kc++) {
        cp_wait0();
        __syncthreads();
        if (kc + 1 < nkc) { load_kv(kc + 1, (kc + 1) & 1); cp_commit(); }

        const float* KtH = sm + KHI_OFF + (kc & 1) * KTILE;
        const float* KtL = sm + KLO_OFF + (kc & 1) * KTILE;
        const float* VtH = sm + VHI_OFF + (kc & 1) * VTILE;
        const float* VtL = sm + VLO_OFF + (kc & 1) * VTILE;

        float sacc[8][4];
        #pragma unroll
        for (int nt = 0; nt < 8; nt++)
            #pragma unroll
            for (int r = 0; r < 4; r++) sacc[nt][r] = 0.f;

        #pragma unroll
        for (int kk = 0; kk < 8; kk++) {
            #pragma unroll
            for (int nt = 0; nt < 8; nt++) {
                const int ko = (nt * 8 + lq) * KST + kk * 8 + lr4;
                uint32_t bh0 = __float_as_uint(KtH[ko]);
                uint32_t bh1 = __float_as_uint(KtH[ko + 4]);
                uint32_t bl0 = __float_as_uint(KtL[ko]);
                uint32_t bl1 = __float_as_uint(KtL[ko + 4]);
                mma_tf32(sacc[nt][0], sacc[nt][1], sacc[nt][2], sacc[nt][3],
                         ql[kk][0], ql[kk][1], ql[kk][2], ql[kk][3], bh0, bh1);
                mma_tf32(sacc[nt][0], sacc[nt][1], sacc[nt][2], sacc[nt][3],
                         qh[kk][0], qh[kk][1], qh[kk][2], qh[kk][3], bl0, bl1);
                mma_tf32(sacc[nt][0], sacc[nt][1], sacc[nt][2], sacc[nt][3],
                         qh[kk][0], qh[kk][1], qh[kk][2], qh[kk][3], bh0, bh1);
            }
        }

        #pragma unroll
        for (int nt = 0; nt < 8; nt++) {
            const int cb = kc * 64 + nt * 8 + 2 * lr4;
            if (cb     >= row0) sacc[nt][0] = -1.0e12f;
            if (cb + 1 >= row0) sacc[nt][1] = -1.0e12f;
            if (cb     >= row1) sacc[nt][2] = -1.0e12f;
            if (cb + 1 >= row1) sacc[nt][3] = -1.0e12f;
        }

        float mt0 = -3.0e38f, mt1 = -3.0e38f;
        #pragma unroll
        for (int nt = 0; nt < 8; nt++) {
            mt0 = fmaxf(mt0, fmaxf(sacc[nt][0], sacc[nt][1]));
            mt1 = fmaxf(mt1, fmaxf(sacc[nt][2], sacc[nt][3]));
        }
        mt0 = fmaxf(mt0, __shfl_xor_sync(0xffffffffu, mt0, 1));
        mt0 = fmaxf(mt0, __shfl_xor_sync(0xffffffffu, mt0, 2));
        mt1 = fmaxf(mt1, __shfl_xor_sync(0xffffffffu, mt1, 1));
        mt1 = fmaxf(mt1, __shfl_xor_sync(0xffffffffu, mt1, 2));
        const float mn0 = fmaxf(m0, mt0);
        const float mn1 = fmaxf(m1, mt1);
        const float sc0 = __expf(m0 - mn0);
        const float sc1 = __expf(m1 - mn1);
        float ls0 = 0.f, ls1 = 0.f;
        #pragma unroll
        for (int nt = 0; nt < 8; nt++) {
            sacc[nt][0] = __expf(sacc[nt][0] - mn0);
            sacc[nt][1] = __expf(sacc[nt][1] - mn0);
            sacc[nt][2] = __expf(sacc[nt][2] - mn1);
            sacc[nt][3] = __expf(sacc[nt][3] - mn1);
            ls0 += sacc[nt][0] + sacc[nt][1];
            ls1 += sacc[nt][2] + sacc[nt][3];
        }
        l0 = l0 * sc0 + ls0;
        l1 = l1 * sc1 + ls1;
        m0 = mn0; m1 = mn1;
        #pragma unroll
        for (int nt = 0; nt < 8; nt++) {
            oacc[nt][0] *= sc0; oacc[nt][1] *= sc0;
            oacc[nt][2] *= sc1; oacc[nt][3] *= sc1;
        }

        #pragma unroll
        for (int nt = 0; nt < 8; nt++) {
            *(float2*)&Pw[lq * PST + nt * 8 + 2 * lr4] =
                make_float2(sacc[nt][0], sacc[nt][1]);
            *(float2*)&Pw[(lq + 8) * PST + nt * 8 + 2 * lr4] =
                make_float2(sacc[nt][2], sacc[nt][3]);
        }
        __syncwarp();

        #pragma unroll
        for (int kk = 0; kk < 8; kk++) {
            const int c = kk * 8 + lr4;
            uint32_t ph[4];
            ph[0] = f2tf32(Pw[lq * PST + c]);
            ph[1] = f2tf32(Pw[(lq + 8) * PST + c]);
            ph[2] = f2tf32(Pw[lq * PST + c + 4]);
            ph[3] = f2tf32(Pw[(lq + 8) * PST + c + 4]);
            #pragma unroll
            for (int nt = 0; nt < 8; nt++) {
                const int v0o = (kk * 8 + lr4) * VST + nt * 8 + lq;
                const int v1o = (kk * 8 + lr4 + 4) * VST + nt * 8 + lq;
                uint32_t vh0 = __float_as_uint(VtH[v0o]);
                uint32_t vh1 = __float_as_uint(VtH[v1o]);
                uint32_t vl0 = __float_as_uint(VtL[v0o]);
                uint32_t vl1 = __float_as_uint(VtL[v1o]);
                mma_tf32(oacc[nt][0], oacc[nt][1], oacc[nt][2], oacc[nt][3],
                         ph[0], ph[1], ph[2], ph[3], vl0, vl1);
                mma_tf32(oacc[nt][0], oacc[nt][1], oacc[nt][2], oacc[nt][3],
                         ph[0], ph[1], ph[2], ph[3], vh0, vh1);
            }
        }
        __syncwarp();
    }

    l0 += __shfl_xor_sync(0xffffffffu, l0, 1);
    l0 += __shfl_xor_sync(0xffffffffu, l0, 2);
    l1 += __shfl_xor_sync(0xffffffffu, l1, 1);
    l1 += __shfl_xor_sync(0xffffffffu, l1, 2);
    const float inv0 = 1.f / l0;
    const float inv1 = 1.f / l1;

    const size_t obase = ((size_t)b * Sseq + (size_t)t * 128 + warp * 16) * Fdim + h * Dh;
    #pragma unroll
    for (int nt = 0; nt < 8; nt++) {
        const int cb = nt * 8 + 2 * lr4;
        float v00 = oacc[nt][0] * inv0, v01 = oacc[nt][1] * inv0;
        float v10 = oacc[nt][2] * inv1, v11 = oacc[nt][3] * inv1;
        uint32_t h00 = f2tf32(v00), h01 = f2tf32(v01);
        uint32_t h10 = f2tf32(v10), h11 = f2tf32(v11);
        const size_t o0 = obase + (size_t)lq * Fdim + cb;
        const size_t o1 = obase + (size_t)(lq + 8) * Fdim + cb;
        *(float2*)&Ohi[o0] = make_float2(__uint_as_float(h00), __uint_as_float(h01));
        *(float2*)&Ohi[o1] = make_float2(__uint_as_float(h10), __uint_as_float(h11));
        *(float2*)&Olo[o0] = make_float2(v00 - __uint_as_float(h00), v01 - __uint_as_float(h01));
        *(float2*)&Olo[o1] = make_float2(v10 - __uint_as_float(h10), v11 - __uint_as_float(h11));
    }
}

// ---------------------------------------------------------------------------
extern "C" void kernel_launch(void* const* d_in, const int* in_sizes, int n_in,
                              void* d_out, int out_size)
{
    (void)in_sizes; (void)n_in; (void)out_size;
    const float* attend_from = (const float*)d_in[0];
    const float* attend_to   = (const float*)d_in[1];
    const float* w_q   = (const float*)d_in[2];
    const float* b_q   = (const float*)d_in[3];
    const float* w_kv  = (const float*)d_in[4];
    const float* b_kv  = (const float*)d_in[5];
    const float* w_out = (const float*)d_in[6];
    const float* b_out = (const float*)d_in[7];
    float* out = (float*)d_out;

    float *xfhi, *xflo, *xthi, *xtlo, *wqhi, *wqlo, *wkvhi, *wkvlo, *wohi, *wolo;
    float *qhi, *qlo, *khi, *klo, *vhi, *vlo, *ohi, *olo;
    cudaGetSymbolAddress((void**)&xfhi, g_Xfhi);
    cudaGetSymbolAddress((void**)&xflo, g_Xflo);
    cudaGetSymbolAddress((void**)&xthi, g_Xthi);
    cudaGetSymbolAddress((void**)&xtlo, g_Xtlo);
    cudaGetSymbolAddress((void**)&wqhi, g_Wqhi);
    cudaGetSymbolAddress((void**)&wqlo, g_Wqlo);
    cudaGetSymbolAddress((void**)&wkvhi, g_Wkvhi);
    cudaGetSymbolAddress((void**)&wkvlo, g_Wkvlo);
    cudaGetSymbolAddress((void**)&wohi, g_Wohi);
    cudaGetSymbolAddress((void**)&wolo, g_Wolo);
    cudaGetSymbolAddress((void**)&qhi, g_Qhi);
    cudaGetSymbolAddress((void**)&qlo, g_Qlo);
    cudaGetSymbolAddress((void**)&khi, g_Khi);
    cudaGetSymbolAddress((void**)&klo, g_Klo);
    cudaGetSymbolAddress((void**)&vhi, g_Vhi);
    cudaGetSymbolAddress((void**)&vlo, g_Vlo);
    cudaGetSymbolAddress((void**)&ohi, g_Ohi);
    cudaGetSymbolAddress((void**)&olo, g_Olo);

    cudaFuncSetAttribute(qkv_gemm_kernel,
                         cudaFuncAttributeMaxDynamicSharedMemorySize, GEMM_SMEM);
    cudaFuncSetAttribute(out_gemm_kernel,
                         cudaFuncAttributeMaxDynamicSharedMemorySize, GEMM_SMEM);
    cudaFuncSetAttribute(flash_mma_kernel,
                         cudaFuncAttributeMaxDynamicSharedMemorySize, FLASH_SMEM);

    // 0) Pre-split all GEMM operands into tf32 hi/lo
    {
        const int nXf = Mrows * Fdim / 4;        // 1M float4
        const int nWq = Fdim * Fdim / 4;         // 256K
        const int nWkv = Fdim * 2 * Fdim / 4;    // 512K
        split_kernel<<<(nXf + 255) / 256, 256>>>(attend_from, xfhi, xflo, nXf);
        split_kernel<<<(nXf + 255) / 256, 256>>>(attend_to,   xthi, xtlo, nXf);
        split_kernel<<<(nWq + 255) / 256, 256>>>(w_q,   wqhi,  wqlo,  nWq);
        split_kernel<<<(nWkv + 255) / 256, 256>>>(w_kv, wkvhi, wkvlo, nWkv);
        split_kernel<<<(nWq + 255) / 256, 256>>>(w_out, wohi,  wolo,  nWq);
    }

    // 1) Q + KV projections, merged (768 CTAs)
    qkv_gemm_kernel<<<768, 256, GEMM_SMEM>>>(
        xfhi, xflo, xthi, xtlo, wqhi, wqlo, wkvhi, wkvlo, b_q, b_kv,
        qhi, qlo, khi, klo, vhi, vlo);

    // 2) Tensor-core flash attention
    {
        dim3 grid(Sseq / 128, Hh, Bsz);
        flash_mma_kernel<<<grid, 256, FLASH_SMEM>>>(
            qhi, qlo, khi, klo, vhi, vlo, ohi, olo);
    }

    // 3) Output projection
    {
        dim3 grid(Fdim / 128, Mrows / 128);
        out_gemm_kernel<<<grid, 256, GEMM_SMEM>>>(
            ohi, olo, wohi, wolo, b_out, out);
    }
}